// round 2
// baseline (speedup 1.0000x reference)
#include <cuda_runtime.h>
#include <cstdint>

#define N_NODES 100000
#define N_EDGES 1600000

__device__ int   g_is64;
__device__ int   g_cnt[N_NODES];
__device__ int   g_fill[N_NODES];
__device__ float g_dis[N_NODES];
__device__ int   g_rowptr[N_NODES + 1];
__device__ int   g_bsum[256];
__device__ int   g_bofs[256];
__device__ int   g_colsrc[N_EDGES];
__device__ __align__(16) float g_bufA[(size_t)N_NODES * 128];
__device__ __align__(16) float g_bufB[(size_t)N_NODES * 128];
__device__ __align__(16) float g_s32a[(size_t)N_NODES * 32];
__device__ __align__(16) float g_s32b[(size_t)N_NODES * 32];

// ---- dtype detection: int64 edge ids have zero high words (ids < 2^31) ----
__global__ void k_detect(const int* __restrict__ w, int E) {
    __shared__ int any;
    if (threadIdx.x == 0) any = 0;
    __syncthreads();
    int n = min(2048, E);             // reads 2*n ints <= 2E, safe for both dtypes
    int local = 0;
    for (int i = threadIdx.x; i < n; i += blockDim.x) local |= w[2 * i + 1];
    if (local) atomicOr(&any, 1);
    __syncthreads();
    if (threadIdx.x == 0) g_is64 = (any == 0) ? 1 : 0;
}

__device__ __forceinline__ int edge_at(const void* ed, size_t idx) {
    return g_is64 ? (int)((const long long*)ed)[idx] : ((const int*)ed)[idx];
}

__global__ void k_init(int N) {
    int i = blockIdx.x * blockDim.x + threadIdx.x;
    if (i < N) g_cnt[i] = 0;
}

__global__ void k_count(const void* __restrict__ edges, int E, int N) {
    int e = blockIdx.x * blockDim.x + threadIdx.x;
    if (e >= E) return;
    int d = edge_at(edges, (size_t)E + e);
    if ((unsigned)d >= (unsigned)N) return;
    atomicAdd(&g_cnt[d], 1);
}

__global__ void k_dis(int N) {
    int i = blockIdx.x * blockDim.x + threadIdx.x;
    if (i >= N) return;
    g_dis[i] = rsqrtf((float)(g_cnt[i] + 1));   // +1 self-loop
    g_fill[i] = 0;
}

__global__ void scan_reduce(int N) {
    __shared__ int sm[1024];
    int idx = blockIdx.x * 1024 + threadIdx.x;
    sm[threadIdx.x] = (idx < N) ? g_cnt[idx] : 0;
    __syncthreads();
    for (int s = 512; s > 0; s >>= 1) {
        if (threadIdx.x < s) sm[threadIdx.x] += sm[threadIdx.x + s];
        __syncthreads();
    }
    if (threadIdx.x == 0) g_bsum[blockIdx.x] = sm[0];
}

__global__ void scan_top(int nb, int N) {
    if (threadIdx.x == 0) {
        int run = 0;
        for (int b = 0; b < nb; b++) { g_bofs[b] = run; run += g_bsum[b]; }
        g_rowptr[N] = run;            // total counted edges (== E when ids valid)
    }
}

__global__ void scan_write(int N) {
    __shared__ int sm[1024];
    int idx = blockIdx.x * 1024 + threadIdx.x;
    int v = (idx < N) ? g_cnt[idx] : 0;
    sm[threadIdx.x] = v;
    __syncthreads();
    for (int off = 1; off < 1024; off <<= 1) {
        int t = (threadIdx.x >= off) ? sm[threadIdx.x - off] : 0;
        __syncthreads();
        sm[threadIdx.x] += t;
        __syncthreads();
    }
    if (idx < N) g_rowptr[idx] = g_bofs[blockIdx.x] + sm[threadIdx.x] - v;  // exclusive
}

__global__ void fill_csr(const void* __restrict__ edges, int E, int N) {
    int e = blockIdx.x * blockDim.x + threadIdx.x;
    if (e >= E) return;
    int s = edge_at(edges, e);
    int d = edge_at(edges, (size_t)E + e);
    if ((unsigned)s >= (unsigned)N || (unsigned)d >= (unsigned)N) return;
    int pos = g_rowptr[d] + atomicAdd(&g_fill[d], 1);
    g_colsrc[pos] = s;
}

// ---- fused GEMM (+bias+relu epilogue): Y[N,NOUT] = X[N,K] @ W[K,NOUT] ----
template <int K, int NOUT, bool EPI>
__global__ __launch_bounds__(256) void gemm_kernel(
    const float* __restrict__ X, const float* __restrict__ W,
    const float* __restrict__ B, float* __restrict__ Y, int N)
{
    constexpr int TR = 64, KT = 32, TN = NOUT / 32, TM = 8;
    constexpr int XS = TR + 4;
    __shared__ float xs[KT * XS];
    __shared__ float ws[KT * NOUT];
    const int tid = threadIdx.x;
    const int colg = tid & 31, rowg = tid >> 5;
    const int row0 = blockIdx.x * TR;

    float acc[TM][TN];
#pragma unroll
    for (int m = 0; m < TM; m++)
#pragma unroll
        for (int n = 0; n < TN; n++) acc[m][n] = 0.f;

    for (int kt = 0; kt < K; kt += KT) {
        for (int idx = tid; idx < KT * NOUT; idx += 256)
            ws[idx] = W[(size_t)(kt + idx / NOUT) * NOUT + (idx % NOUT)];
        for (int idx = tid; idx < TR * KT; idx += 256) {
            int r = idx >> 5, kk = idx & 31;
            int grow = row0 + r;
            xs[kk * XS + r] = (grow < N) ? X[(size_t)grow * K + kt + kk] : 0.f;
        }
        __syncthreads();
#pragma unroll
        for (int kk = 0; kk < KT; kk++) {
            float4 xa = *(const float4*)&xs[kk * XS + rowg * TM];
            float4 xb = *(const float4*)&xs[kk * XS + rowg * TM + 4];
            float xv[TM] = {xa.x, xa.y, xa.z, xa.w, xb.x, xb.y, xb.z, xb.w};
            float wv[TN];
            if constexpr (TN == 4) {
                float4 w4 = *(const float4*)&ws[kk * NOUT + colg * 4];
                wv[0] = w4.x; wv[1] = w4.y; wv[2] = w4.z; wv[3] = w4.w;
            } else {
                wv[0] = ws[kk * NOUT + colg];
            }
#pragma unroll
            for (int m = 0; m < TM; m++)
#pragma unroll
                for (int n = 0; n < TN; n++)
                    acc[m][n] = fmaf(xv[m], wv[n], acc[m][n]);
        }
        __syncthreads();
    }

#pragma unroll
    for (int m = 0; m < TM; m++) {
        int grow = row0 + rowg * TM + m;
        if (grow >= N) continue;
        if constexpr (TN == 4) {
            float4 o = make_float4(acc[m][0], acc[m][1], acc[m][2], acc[m][3]);
            if constexpr (EPI) {
                float4 b4 = *(const float4*)&B[colg * 4];
                o.x = fmaxf(o.x + b4.x, 0.f);
                o.y = fmaxf(o.y + b4.y, 0.f);
                o.z = fmaxf(o.z + b4.z, 0.f);
                o.w = fmaxf(o.w + b4.w, 0.f);
            }
            *(float4*)&Y[(size_t)grow * NOUT + colg * 4] = o;
        } else {
            float v = acc[m][0];
            if constexpr (EPI) v = fmaxf(v + B[colg], 0.f);
            Y[(size_t)grow * NOUT + colg] = v;
        }
    }
}

// ---- CSR gather-aggregation (warp per node):
// out[i] = dis[i] * ( sum_e dis[src]*H[src] + dis[i]*H[i] )  [+ b, relu]
template <int F, bool EPI>
__global__ __launch_bounds__(256) void agg_kernel(
    const float* __restrict__ H, const float* __restrict__ B,
    float* __restrict__ out, int N)
{
    int gw = (blockIdx.x * 256 + threadIdx.x) >> 5;
    int lane = threadIdx.x & 31;
    if (gw >= N) return;
    const float di = g_dis[gw];
    const int beg = g_rowptr[gw], end = g_rowptr[gw + 1];

    if constexpr (F == 128) {
        float4 h0 = ((const float4*)(H + (size_t)gw * 128))[lane];
        float4 acc = make_float4(di * h0.x, di * h0.y, di * h0.z, di * h0.w);
        int e = beg;
        for (; e + 4 <= end; e += 4) {
            int s0 = g_colsrc[e], s1 = g_colsrc[e + 1];
            int s2 = g_colsrc[e + 2], s3 = g_colsrc[e + 3];
            float w0 = g_dis[s0], w1 = g_dis[s1], w2 = g_dis[s2], w3 = g_dis[s3];
            float4 v0 = ((const float4*)(H + (size_t)s0 * 128))[lane];
            float4 v1 = ((const float4*)(H + (size_t)s1 * 128))[lane];
            float4 v2 = ((const float4*)(H + (size_t)s2 * 128))[lane];
            float4 v3 = ((const float4*)(H + (size_t)s3 * 128))[lane];
            acc.x = fmaf(w0, v0.x, acc.x); acc.y = fmaf(w0, v0.y, acc.y);
            acc.z = fmaf(w0, v0.z, acc.z); acc.w = fmaf(w0, v0.w, acc.w);
            acc.x = fmaf(w1, v1.x, acc.x); acc.y = fmaf(w1, v1.y, acc.y);
            acc.z = fmaf(w1, v1.z, acc.z); acc.w = fmaf(w1, v1.w, acc.w);
            acc.x = fmaf(w2, v2.x, acc.x); acc.y = fmaf(w2, v2.y, acc.y);
            acc.z = fmaf(w2, v2.z, acc.z); acc.w = fmaf(w2, v2.w, acc.w);
            acc.x = fmaf(w3, v3.x, acc.x); acc.y = fmaf(w3, v3.y, acc.y);
            acc.z = fmaf(w3, v3.z, acc.z); acc.w = fmaf(w3, v3.w, acc.w);
        }
        for (; e < end; e++) {
            int s = g_colsrc[e];
            float w = g_dis[s];
            float4 v = ((const float4*)(H + (size_t)s * 128))[lane];
            acc.x = fmaf(w, v.x, acc.x); acc.y = fmaf(w, v.y, acc.y);
            acc.z = fmaf(w, v.z, acc.z); acc.w = fmaf(w, v.w, acc.w);
        }
        acc.x *= di; acc.y *= di; acc.z *= di; acc.w *= di;
        if constexpr (EPI) {
            float4 b4 = ((const float4*)B)[lane];
            acc.x = fmaxf(acc.x + b4.x, 0.f); acc.y = fmaxf(acc.y + b4.y, 0.f);
            acc.z = fmaxf(acc.z + b4.z, 0.f); acc.w = fmaxf(acc.w + b4.w, 0.f);
        }
        ((float4*)(out + (size_t)gw * 128))[lane] = acc;
    } else {
        float acc = di * H[(size_t)gw * 32 + lane];
        int e = beg;
        for (; e + 4 <= end; e += 4) {
            int s0 = g_colsrc[e], s1 = g_colsrc[e + 1];
            int s2 = g_colsrc[e + 2], s3 = g_colsrc[e + 3];
            float w0 = g_dis[s0], w1 = g_dis[s1], w2 = g_dis[s2], w3 = g_dis[s3];
            float v0 = H[(size_t)s0 * 32 + lane];
            float v1 = H[(size_t)s1 * 32 + lane];
            float v2 = H[(size_t)s2 * 32 + lane];
            float v3 = H[(size_t)s3 * 32 + lane];
            acc = fmaf(w0, v0, acc);
            acc = fmaf(w1, v1, acc);
            acc = fmaf(w2, v2, acc);
            acc = fmaf(w3, v3, acc);
        }
        for (; e < end; e++) {
            int s = g_colsrc[e];
            acc = fmaf(g_dis[s], H[(size_t)s * 32 + lane], acc);
        }
        acc *= di;
        if constexpr (EPI) acc = fmaxf(acc + B[lane], 0.f);
        out[(size_t)gw * 32 + lane] = acc;
    }
}

extern "C" void kernel_launch(void* const* d_in, const int* in_sizes, int n_in,
                              void* d_out, int out_size) {
    const float* x  = (const float*)d_in[0];
    const void*  ed = d_in[1];
    const float* W1 = (const float*)d_in[2];
    const float* b1 = (const float*)d_in[3];
    const float* W2 = (const float*)d_in[4];
    const float* b2 = (const float*)d_in[5];
    const float* W3 = (const float*)d_in[6];
    const float* b3 = (const float*)d_in[7];
    float* out = (float*)d_out;

    const int N = in_sizes[0] / 32;   // 100000
    const int E = in_sizes[1] / 2;    // 1600000 (element count is dtype-invariant)
    const int nb = (N + 1023) / 1024;

    float *bufA, *bufB, *s32a, *s32b;
    cudaGetSymbolAddress((void**)&bufA, g_bufA);
    cudaGetSymbolAddress((void**)&bufB, g_bufB);
    cudaGetSymbolAddress((void**)&s32a, g_s32a);
    cudaGetSymbolAddress((void**)&s32b, g_s32b);

    const int nblk = (N + 255) / 256;
    const int eblk = (E + 255) / 256;
    const int ablk = (N * 32 + 255) / 256;   // warp per node
    const int gblk = (N + 63) / 64;

    k_detect<<<1, 256>>>((const int*)ed, E);
    k_init<<<nblk, 256>>>(N);
    k_count<<<eblk, 256>>>(ed, E, N);
    k_dis<<<nblk, 256>>>(N);
    scan_reduce<<<nb, 1024>>>(N);
    scan_top<<<1, 32>>>(nb, N);
    scan_write<<<nb, 1024>>>(N);
    fill_csr<<<eblk, 256>>>(ed, E, N);

    // L1: relu(Agg(x) @ W1 + b1)   (Agg commutes with the linear transform)
    agg_kernel<32, false><<<ablk, 256>>>(x, nullptr, s32a, N);
    gemm_kernel<32, 128, true><<<gblk, 256>>>(s32a, W1, b1, bufA, N);

    // L2: relu(Agg(h1) @ W2 + b2)
    agg_kernel<128, false><<<ablk, 256>>>(bufA, nullptr, bufB, N);
    gemm_kernel<128, 128, true><<<gblk, 256>>>(bufB, W2, b2, bufA, N);

    // L3: relu(Agg(h2 @ W3) + b3)  (transform first: aggregate at 32 features)
    gemm_kernel<128, 32, false><<<gblk, 256>>>(bufA, W3, nullptr, s32b, N);
    agg_kernel<32, true><<<ablk, 256>>>(s32b, b3, out, N);
}

// round 5
// speedup vs baseline: 1.0870x; 1.0870x over previous
#include <cuda_runtime.h>
#include <cuda_fp16.h>
#include <cstdint>

#define N_NODES 100000
#define N_EDGES 1600000

__device__ int   g_is64;
__device__ int   g_cnt[N_NODES];
__device__ int   g_fill[N_NODES];
__device__ float g_dis[N_NODES];
__device__ int   g_rowptr[N_NODES + 1];
__device__ int   g_bsum[256];
__device__ int   g_bofs[256];
__device__ int   g_colsrc[N_EDGES];
__device__ __align__(16) float  g_bufA[(size_t)N_NODES * 128];
__device__ __align__(16) float  g_bufB[(size_t)N_NODES * 128];
__device__ __align__(16) __half g_h16[(size_t)N_NODES * 128];
__device__ __align__(16) float  g_s32a[(size_t)N_NODES * 32];
__device__ __align__(16) float  g_s32b[(size_t)N_NODES * 32];

// ---------------- f32x2 packed-FMA helpers (Blackwell FFMA2) ----------------
__device__ __forceinline__ unsigned long long f2x2_bcast(float x) {
    unsigned long long r;
    asm("mov.b64 %0, {%1, %1};" : "=l"(r) : "f"(x));
    return r;
}
__device__ __forceinline__ unsigned long long f2x2_fma(
    unsigned long long a, unsigned long long b, unsigned long long c) {
    unsigned long long d;
    asm("fma.rn.f32x2 %0, %1, %2, %3;" : "=l"(d) : "l"(a), "l"(b), "l"(c));
    return d;
}
__device__ __forceinline__ float2 f2x2_unpack(unsigned long long v) {
    float lo, hi;
    asm("mov.b64 {%0, %1}, %2;" : "=f"(lo), "=f"(hi) : "l"(v));
    return make_float2(lo, hi);
}

// ---------------- dtype detection: int64 ids have zero high words ----------------
__global__ void k_detect(const int* __restrict__ w, int E) {
    __shared__ int any;
    if (threadIdx.x == 0) any = 0;
    __syncthreads();
    int n = min(2048, E);
    int local = 0;
    for (int i = threadIdx.x; i < n; i += blockDim.x) local |= w[2 * i + 1];
    if (local) atomicOr(&any, 1);
    __syncthreads();
    if (threadIdx.x == 0) g_is64 = (any == 0) ? 1 : 0;
}

__device__ __forceinline__ int edge_at(const void* ed, size_t idx) {
    return g_is64 ? (int)((const long long*)ed)[idx] : ((const int*)ed)[idx];
}

__global__ void k_init(int N) {
    int i = blockIdx.x * blockDim.x + threadIdx.x;
    if (i < N) g_cnt[i] = 0;
}

__global__ void k_count(const void* __restrict__ edges, int E, int N) {
    int e = blockIdx.x * blockDim.x + threadIdx.x;
    if (e >= E) return;
    int d = edge_at(edges, (size_t)E + e);
    if ((unsigned)d >= (unsigned)N) return;
    atomicAdd(&g_cnt[d], 1);
}

__global__ void k_dis(int N) {
    int i = blockIdx.x * blockDim.x + threadIdx.x;
    if (i >= N) return;
    g_dis[i] = rsqrtf((float)(g_cnt[i] + 1));   // +1 self-loop
    g_fill[i] = 0;
}

__global__ void scan_reduce(int N) {
    __shared__ int sm[1024];
    int idx = blockIdx.x * 1024 + threadIdx.x;
    sm[threadIdx.x] = (idx < N) ? g_cnt[idx] : 0;
    __syncthreads();
    for (int s = 512; s > 0; s >>= 1) {
        if (threadIdx.x < s) sm[threadIdx.x] += sm[threadIdx.x + s];
        __syncthreads();
    }
    if (threadIdx.x == 0) g_bsum[blockIdx.x] = sm[0];
}

__global__ void scan_top(int nb, int N) {
    if (threadIdx.x == 0) {
        int run = 0;
        for (int b = 0; b < nb; b++) { g_bofs[b] = run; run += g_bsum[b]; }
        g_rowptr[N] = run;
    }
}

__global__ void scan_write(int N) {
    __shared__ int sm[1024];
    int idx = blockIdx.x * 1024 + threadIdx.x;
    int v = (idx < N) ? g_cnt[idx] : 0;
    sm[threadIdx.x] = v;
    __syncthreads();
    for (int off = 1; off < 1024; off <<= 1) {
        int t = (threadIdx.x >= off) ? sm[threadIdx.x - off] : 0;
        __syncthreads();
        sm[threadIdx.x] += t;
        __syncthreads();
    }
    if (idx < N) g_rowptr[idx] = g_bofs[blockIdx.x] + sm[threadIdx.x] - v;
}

__global__ void fill_csr(const void* __restrict__ edges, int E, int N) {
    int e = blockIdx.x * blockDim.x + threadIdx.x;
    if (e >= E) return;
    int s = edge_at(edges, e);
    int d = edge_at(edges, (size_t)E + e);
    if ((unsigned)s >= (unsigned)N || (unsigned)d >= (unsigned)N) return;
    int pos = g_rowptr[d] + atomicAdd(&g_fill[d], 1);
    g_colsrc[pos] = s;
}

// ---------------- GEMM with packed f32x2 FMA ----------------
// Y[N,NOUT] = X[N,K] @ W[K,NOUT]  (+bias, relu). OUT16 writes fp16 to Y16.
template <int K, int NOUT, bool EPI, bool OUT16>
__global__ __launch_bounds__(256) void gemm_kernel(
    const float* __restrict__ X, const float* __restrict__ W,
    const float* __restrict__ B, float* __restrict__ Y,
    __half* __restrict__ Y16, int N)
{
    constexpr int TR = 64, KT = 32, TN = NOUT / 32, TM = 8, TP = TM / 2;
    constexpr int XS = TR + 4;
    __shared__ float xs[KT * XS];
    __shared__ float ws[KT * NOUT];
    const int tid = threadIdx.x;
    const int colg = tid & 31, rowg = tid >> 5;
    const int row0 = blockIdx.x * TR;

    // accp[p][n] = (acc[2p][n], acc[2p+1][n]) packed f32x2
    unsigned long long accp[TP][TN];
#pragma unroll
    for (int p = 0; p < TP; p++)
#pragma unroll
        for (int n = 0; n < TN; n++) accp[p][n] = 0ull;

    for (int kt = 0; kt < K; kt += KT) {
        for (int idx = tid; idx < KT * NOUT; idx += 256)
            ws[idx] = W[(size_t)(kt + idx / NOUT) * NOUT + (idx % NOUT)];
        for (int idx = tid; idx < TR * KT; idx += 256) {
            int r = idx >> 5, kk = idx & 31;
            int grow = row0 + r;
            xs[kk * XS + r] = (grow < N) ? X[(size_t)grow * K + kt + kk] : 0.f;
        }
        __syncthreads();
#pragma unroll
        for (int kk = 0; kk < KT; kk++) {
            // x pairs come pre-packed straight from LDS.64 (broadcast across warp)
            unsigned long long xp[TP];
#pragma unroll
            for (int p = 0; p < TP; p++)
                xp[p] = *(const unsigned long long*)&xs[kk * XS + rowg * TM + 2 * p];
            if constexpr (TN == 4) {
                float4 w4 = *(const float4*)&ws[kk * NOUT + colg * 4];
                unsigned long long wb[4] = {f2x2_bcast(w4.x), f2x2_bcast(w4.y),
                                            f2x2_bcast(w4.z), f2x2_bcast(w4.w)};
#pragma unroll
                for (int p = 0; p < TP; p++)
#pragma unroll
                    for (int n = 0; n < 4; n++)
                        accp[p][n] = f2x2_fma(xp[p], wb[n], accp[p][n]);
            } else {
                unsigned long long wb = f2x2_bcast(ws[kk * NOUT + colg]);
#pragma unroll
                for (int p = 0; p < TP; p++)
                    accp[p][0] = f2x2_fma(xp[p], wb, accp[p][0]);
            }
        }
        __syncthreads();
    }

#pragma unroll
    for (int p = 0; p < TP; p++) {
        float2 un[TN];
#pragma unroll
        for (int n = 0; n < TN; n++) un[n] = f2x2_unpack(accp[p][n]);
#pragma unroll
        for (int half = 0; half < 2; half++) {
            int grow = row0 + rowg * TM + 2 * p + half;
            if (grow >= N) continue;
            if constexpr (TN == 4) {
                float4 o = make_float4(half ? un[0].y : un[0].x, half ? un[1].y : un[1].x,
                                       half ? un[2].y : un[2].x, half ? un[3].y : un[3].x);
                if constexpr (EPI) {
                    float4 b4 = *(const float4*)&B[colg * 4];
                    o.x = fmaxf(o.x + b4.x, 0.f);
                    o.y = fmaxf(o.y + b4.y, 0.f);
                    o.z = fmaxf(o.z + b4.z, 0.f);
                    o.w = fmaxf(o.w + b4.w, 0.f);
                }
                if constexpr (OUT16) {
                    __half2 h01 = __floats2half2_rn(o.x, o.y);
                    __half2 h23 = __floats2half2_rn(o.z, o.w);
                    uint2 pk = make_uint2(*(unsigned*)&h01, *(unsigned*)&h23);
                    *(uint2*)&Y16[(size_t)grow * NOUT + colg * 4] = pk;
                } else {
                    *(float4*)&Y[(size_t)grow * NOUT + colg * 4] = o;
                }
            } else {
                float v = half ? un[0].y : un[0].x;
                if constexpr (EPI) v = fmaxf(v + B[colg], 0.f);
                Y[(size_t)grow * NOUT + colg] = v;
            }
        }
    }
}

// ---------------- agg, F=32, fp32 (warp per node) ----------------
template <bool EPI>
__global__ __launch_bounds__(256) void agg32_kernel(
    const float* __restrict__ H, const float* __restrict__ B,
    float* __restrict__ out, int N)
{
    int gw = (blockIdx.x * 256 + threadIdx.x) >> 5;
    int lane = threadIdx.x & 31;
    if (gw >= N) return;
    const float di = g_dis[gw];
    const int beg = g_rowptr[gw], end = g_rowptr[gw + 1];

    float acc = di * H[(size_t)gw * 32 + lane];
    int e = beg;
    for (; e + 4 <= end; e += 4) {
        int s0 = g_colsrc[e], s1 = g_colsrc[e + 1];
        int s2 = g_colsrc[e + 2], s3 = g_colsrc[e + 3];
        float w0 = g_dis[s0], w1 = g_dis[s1], w2 = g_dis[s2], w3 = g_dis[s3];
        float v0 = H[(size_t)s0 * 32 + lane];
        float v1 = H[(size_t)s1 * 32 + lane];
        float v2 = H[(size_t)s2 * 32 + lane];
        float v3 = H[(size_t)s3 * 32 + lane];
        acc = fmaf(w0, v0, acc);
        acc = fmaf(w1, v1, acc);
        acc = fmaf(w2, v2, acc);
        acc = fmaf(w3, v3, acc);
    }
    for (; e < end; e++) {
        int s = g_colsrc[e];
        acc = fmaf(g_dis[s], H[(size_t)s * 32 + lane], acc);
    }
    acc *= di;
    if constexpr (EPI) acc = fmaxf(acc + B[lane], 0.f);
    out[(size_t)gw * 32 + lane] = acc;
}

// ---------------- agg, F=128, fp16 gather -> fp32 accumulate ----------------
__device__ __forceinline__ float4 h4_to_f4(uint2 v) {
    __half2 a = *(__half2*)&v.x, b = *(__half2*)&v.y;
    float2 fa = __half22float2(a), fb = __half22float2(b);
    return make_float4(fa.x, fa.y, fb.x, fb.y);
}

__global__ __launch_bounds__(256) void agg128h_kernel(
    const __half* __restrict__ H, float* __restrict__ out, int N)
{
    int gw = (blockIdx.x * 256 + threadIdx.x) >> 5;
    int lane = threadIdx.x & 31;
    if (gw >= N) return;
    const float di = g_dis[gw];
    const int beg = g_rowptr[gw], end = g_rowptr[gw + 1];

    float4 h0 = h4_to_f4(((const uint2*)(H + (size_t)gw * 128))[lane]);
    float4 acc = make_float4(di * h0.x, di * h0.y, di * h0.z, di * h0.w);
    int e = beg;
    for (; e + 4 <= end; e += 4) {
        int s0 = g_colsrc[e], s1 = g_colsrc[e + 1];
        int s2 = g_colsrc[e + 2], s3 = g_colsrc[e + 3];
        float w0 = g_dis[s0], w1 = g_dis[s1], w2 = g_dis[s2], w3 = g_dis[s3];
        float4 v0 = h4_to_f4(((const uint2*)(H + (size_t)s0 * 128))[lane]);
        float4 v1 = h4_to_f4(((const uint2*)(H + (size_t)s1 * 128))[lane]);
        float4 v2 = h4_to_f4(((const uint2*)(H + (size_t)s2 * 128))[lane]);
        float4 v3 = h4_to_f4(((const uint2*)(H + (size_t)s3 * 128))[lane]);
        acc.x = fmaf(w0, v0.x, acc.x); acc.y = fmaf(w0, v0.y, acc.y);
        acc.z = fmaf(w0, v0.z, acc.z); acc.w = fmaf(w0, v0.w, acc.w);
        acc.x = fmaf(w1, v1.x, acc.x); acc.y = fmaf(w1, v1.y, acc.y);
        acc.z = fmaf(w1, v1.z, acc.z); acc.w = fmaf(w1, v1.w, acc.w);
        acc.x = fmaf(w2, v2.x, acc.x); acc.y = fmaf(w2, v2.y, acc.y);
        acc.z = fmaf(w2, v2.z, acc.z); acc.w = fmaf(w2, v2.w, acc.w);
        acc.x = fmaf(w3, v3.x, acc.x); acc.y = fmaf(w3, v3.y, acc.y);
        acc.z = fmaf(w3, v3.z, acc.z); acc.w = fmaf(w3, v3.w, acc.w);
    }
    for (; e < end; e++) {
        int s = g_colsrc[e];
        float w = g_dis[s];
        float4 v = h4_to_f4(((const uint2*)(H + (size_t)s * 128))[lane]);
        acc.x = fmaf(w, v.x, acc.x); acc.y = fmaf(w, v.y, acc.y);
        acc.z = fmaf(w, v.z, acc.z); acc.w = fmaf(w, v.w, acc.w);
    }
    acc.x *= di; acc.y *= di; acc.z *= di; acc.w *= di;
    // lane covers features [4*lane, 4*lane+4)
    float4* dst = (float4*)(out + (size_t)gw * 128);
    dst[lane] = acc;
}

extern "C" void kernel_launch(void* const* d_in, const int* in_sizes, int n_in,
                              void* d_out, int out_size) {
    const float* x  = (const float*)d_in[0];
    const void*  ed = d_in[1];
    const float* W1 = (const float*)d_in[2];
    const float* b1 = (const float*)d_in[3];
    const float* W2 = (const float*)d_in[4];
    const float* b2 = (const float*)d_in[5];
    const float* W3 = (const float*)d_in[6];
    const float* b3 = (const float*)d_in[7];
    float* out = (float*)d_out;

    const int N = in_sizes[0] / 32;
    const int E = in_sizes[1] / 2;
    const int nb = (N + 1023) / 1024;

    float  *bufA, *bufB, *s32a, *s32b;
    __half *h16;
    cudaGetSymbolAddress((void**)&bufA, g_bufA);
    cudaGetSymbolAddress((void**)&bufB, g_bufB);
    cudaGetSymbolAddress((void**)&s32a, g_s32a);
    cudaGetSymbolAddress((void**)&s32b, g_s32b);
    cudaGetSymbolAddress((void**)&h16,  g_h16);

    const int nblk = (N + 255) / 256;
    const int eblk = (E + 255) / 256;
    const int ablk = (N * 32 + 255) / 256;   // warp per node
    const int gblk = (N + 63) / 64;

    k_detect<<<1, 256>>>((const int*)ed, E);
    k_init<<<nblk, 256>>>(N);
    k_count<<<eblk, 256>>>(ed, E, N);
    k_dis<<<nblk, 256>>>(N);
    scan_reduce<<<nb, 1024>>>(N);
    scan_top<<<1, 32>>>(nb, N);
    scan_write<<<nb, 1024>>>(N);
    fill_csr<<<eblk, 256>>>(ed, E, N);

    // L1: relu(Agg(x) @ W1 + b1); h1 stored fp16 for the gather-heavy next agg
    agg32_kernel<false><<<ablk, 256>>>(x, nullptr, s32a, N);
    gemm_kernel<32, 128, true, true><<<gblk, 256>>>(s32a, W1, b1, nullptr, h16, N);

    // L2: relu(Agg(h1) @ W2 + b2)
    agg128h_kernel<<<ablk, 256>>>(h16, bufB, N);
    gemm_kernel<128, 128, true, false><<<gblk, 256>>>(bufB, W2, b2, bufA, nullptr, N);

    // L3: relu(Agg(h2 @ W3) + b3)  (transform first: aggregate at 32 features)
    gemm_kernel<128, 32, false, false><<<gblk, 256>>>(bufA, W3, nullptr, s32b, nullptr, N);
    agg32_kernel<true><<<ablk, 256>>>(s32b, b3, out, N);
}

// round 6
// speedup vs baseline: 1.3914x; 1.2800x over previous
#include <cuda_runtime.h>
#include <cuda_fp16.h>
#include <mma.h>
#include <cstdint>
using namespace nvcuda;

#define N_NODES 100000
#define N_EDGES 1600000
#define NPAD    100352   // multiple of 256, >= ceil(N/256)*256 and ceil(N/128)*128

__device__ int   g_is64;
__device__ int   g_cnt[N_NODES];
__device__ int   g_fill[N_NODES];
__device__ float g_dis[N_NODES];
__device__ int   g_rowptr[N_NODES + 1];
__device__ int   g_bsum[256];
__device__ int   g_bofs[256];
__device__ int   g_colsrc[N_EDGES];
__device__ __align__(16) __half g_xh  [(size_t)NPAD * 32];   // x as fp16
__device__ __align__(16) __half g_s32h[(size_t)NPAD * 32];   // Agg(x)
__device__ __align__(16) __half g_h16 [(size_t)NPAD * 128];  // h1
__device__ __align__(16) __half g_hB  [(size_t)NPAD * 128];  // Agg(h1)
__device__ __align__(16) __half g_hA  [(size_t)NPAD * 128];  // h2
__device__ __align__(16) __half g_s3h [(size_t)NPAD * 32];   // h2 @ W3

// ---- prep: zero counts, convert x->fp16, detect edge dtype (block 0) ----
__global__ void k_prep(const float* __restrict__ x, const int* __restrict__ w,
                       int N, int E) {
    int i = blockIdx.x * blockDim.x + threadIdx.x;
    if (i < N) g_cnt[i] = 0;
    if (i < N * 32) g_xh[i] = __float2half(x[i]);
    if (blockIdx.x == 0) {
        __shared__ int any;
        if (threadIdx.x == 0) any = 0;
        __syncthreads();
        int n = min(2048, E);
        int local = 0;
        for (int j = threadIdx.x; j < n; j += blockDim.x) local |= w[2 * j + 1];
        if (local) atomicOr(&any, 1);
        __syncthreads();
        if (threadIdx.x == 0) g_is64 = (any == 0) ? 1 : 0;
    }
}

__device__ __forceinline__ int edge_at(const void* ed, size_t idx) {
    return g_is64 ? (int)((const long long*)ed)[idx] : ((const int*)ed)[idx];
}

__global__ void k_count(const void* __restrict__ edges, int E, int N) {
    int e = blockIdx.x * blockDim.x + threadIdx.x;
    if (e >= E) return;
    int d = edge_at(edges, (size_t)E + e);
    if ((unsigned)d >= (unsigned)N) return;
    atomicAdd(&g_cnt[d], 1);
}

// scan pass 1 + dis/fill init fused
__global__ void scan_reduce(int N) {
    __shared__ int sm[1024];
    int idx = blockIdx.x * 1024 + threadIdx.x;
    int c = (idx < N) ? g_cnt[idx] : 0;
    sm[threadIdx.x] = c;
    if (idx < N) { g_dis[idx] = rsqrtf((float)(c + 1)); g_fill[idx] = 0; }
    __syncthreads();
    for (int s = 512; s > 0; s >>= 1) {
        if (threadIdx.x < s) sm[threadIdx.x] += sm[threadIdx.x + s];
        __syncthreads();
    }
    if (threadIdx.x == 0) g_bsum[blockIdx.x] = sm[0];
}

__global__ void scan_top(int nb, int N) {
    if (threadIdx.x == 0) {
        int run = 0;
        for (int b = 0; b < nb; b++) { g_bofs[b] = run; run += g_bsum[b]; }
        g_rowptr[N] = run;
    }
}

__global__ void scan_write(int N) {
    __shared__ int sm[1024];
    int idx = blockIdx.x * 1024 + threadIdx.x;
    int v = (idx < N) ? g_cnt[idx] : 0;
    sm[threadIdx.x] = v;
    __syncthreads();
    for (int off = 1; off < 1024; off <<= 1) {
        int t = (threadIdx.x >= off) ? sm[threadIdx.x - off] : 0;
        __syncthreads();
        sm[threadIdx.x] += t;
        __syncthreads();
    }
    if (idx < N) g_rowptr[idx] = g_bofs[blockIdx.x] + sm[threadIdx.x] - v;
}

__global__ void fill_csr(const void* __restrict__ edges, int E, int N) {
    int e = blockIdx.x * blockDim.x + threadIdx.x;
    if (e >= E) return;
    int s = edge_at(edges, e);
    int d = edge_at(edges, (size_t)E + e);
    if ((unsigned)s >= (unsigned)N || (unsigned)d >= (unsigned)N) return;
    int pos = g_rowptr[d] + atomicAdd(&g_fill[d], 1);
    g_colsrc[pos] = s;
}

// ---------------- tensor-core GEMM: Y[N,NOUT] = A[N,K](fp16) @ W[K,NOUT](fp32->fp16) ----
// fp32 accumulate; epilogue bias+relu optional; output fp16.
template <int K, int NOUT, bool EPI>
__global__ __launch_bounds__(256) void wgemm(
    const __half* __restrict__ A, const float* __restrict__ Wf,
    const float* __restrict__ Bias, __half* __restrict__ Y)
{
    constexpr int WN = (NOUT == 128) ? 2 : 1;
    constexpr int WM = 8 / WN;
    constexpr int NFRAG = NOUT / (WN * 16);
    constexpr int MFRAG = 2;
    constexpr int MBLK = WM * MFRAG * 16;       // 128 (NOUT=128) / 256 (NOUT=32)
    constexpr int LDA = K + 8;
    constexpr int LDB = NOUT + 8;
    extern __shared__ __half smh[];
    __half* As = smh;                            // MBLK x LDA
    __half* Bs = smh + MBLK * LDA;               // K x LDB
    const int tid = threadIdx.x;
    const int row0 = blockIdx.x * MBLK;          // always < NPAD (padded buffers)

    for (int i = tid; i < K * NOUT; i += 256) {
        int k = i / NOUT, n = i % NOUT;
        Bs[k * LDB + n] = __float2half(Wf[i]);
    }
    constexpr int CH = K / 8;                    // uint4 chunks per row
    for (int i = tid; i < MBLK * CH; i += 256) {
        int r = i / CH, ch = i % CH;
        uint4 v = *(const uint4*)&A[((size_t)(row0 + r)) * K + ch * 8];
        *(uint4*)&As[r * LDA + ch * 8] = v;
    }
    __syncthreads();

    const int wid = tid >> 5;
    const int wm = wid % WM, wn = wid / WM;
    const int mrow = wm * MFRAG * 16;
    const int ncol = wn * NFRAG * 16;

    wmma::fragment<wmma::accumulator, 16, 16, 16, float> acc[MFRAG][NFRAG];
#pragma unroll
    for (int m = 0; m < MFRAG; m++)
#pragma unroll
        for (int n = 0; n < NFRAG; n++) wmma::fill_fragment(acc[m][n], 0.f);

#pragma unroll
    for (int k = 0; k < K; k += 16) {
        wmma::fragment<wmma::matrix_a, 16, 16, 16, __half, wmma::row_major> af[MFRAG];
#pragma unroll
        for (int m = 0; m < MFRAG; m++)
            wmma::load_matrix_sync(af[m], As + (mrow + m * 16) * LDA + k, LDA);
        wmma::fragment<wmma::matrix_b, 16, 16, 16, __half, wmma::row_major> bf[NFRAG];
#pragma unroll
        for (int n = 0; n < NFRAG; n++)
            wmma::load_matrix_sync(bf[n], Bs + k * LDB + ncol + n * 16, LDB);
#pragma unroll
        for (int m = 0; m < MFRAG; m++)
#pragma unroll
            for (int n = 0; n < NFRAG; n++)
                wmma::mma_sync(acc[m][n], af[m], bf[n], acc[m][n]);
    }
    __syncthreads();   // done reading As/Bs; reuse smem as epilogue staging

    float* stage = (float*)smh + wid * 272;      // 8 warps * 1088B
    const int lane = tid & 31;
    const int r = lane >> 1, c0 = (lane & 1) * 8;
#pragma unroll
    for (int m = 0; m < MFRAG; m++)
#pragma unroll
        for (int n = 0; n < NFRAG; n++) {
            wmma::store_matrix_sync(stage, acc[m][n], 16, wmma::mem_row_major);
            __syncwarp();
            int grow = row0 + mrow + m * 16 + r;
            int gcol = ncol + n * 16 + c0;
            __half h[8];
#pragma unroll
            for (int j = 0; j < 8; j++) {
                float v = stage[r * 16 + c0 + j];
                if constexpr (EPI) v = fmaxf(v + Bias[gcol + j], 0.f);
                h[j] = __float2half(v);
            }
            *(uint4*)&Y[(size_t)grow * NOUT + gcol] = *(uint4*)h;
            __syncwarp();
        }
}

// ---------------- agg F=32: half gather -> fp32 accumulate ----------------
// OUTF: write float (final layer, +bias+relu); else write half
template <bool EPI, bool OUTF>
__global__ __launch_bounds__(256) void agg32_kernel(
    const __half* __restrict__ H, const float* __restrict__ B,
    __half* __restrict__ outh, float* __restrict__ outf, int N)
{
    int gw = (blockIdx.x * 256 + threadIdx.x) >> 5;
    int lane = threadIdx.x & 31;
    if (gw >= N) return;
    const float di = g_dis[gw];
    const int beg = g_rowptr[gw], end = g_rowptr[gw + 1];

    float acc = di * __half2float(H[(size_t)gw * 32 + lane]);
    int e = beg;
    for (; e + 4 <= end; e += 4) {
        int s0 = g_colsrc[e], s1 = g_colsrc[e + 1];
        int s2 = g_colsrc[e + 2], s3 = g_colsrc[e + 3];
        float w0 = g_dis[s0], w1 = g_dis[s1], w2 = g_dis[s2], w3 = g_dis[s3];
        float v0 = __half2float(H[(size_t)s0 * 32 + lane]);
        float v1 = __half2float(H[(size_t)s1 * 32 + lane]);
        float v2 = __half2float(H[(size_t)s2 * 32 + lane]);
        float v3 = __half2float(H[(size_t)s3 * 32 + lane]);
        acc = fmaf(w0, v0, acc);
        acc = fmaf(w1, v1, acc);
        acc = fmaf(w2, v2, acc);
        acc = fmaf(w3, v3, acc);
    }
    for (; e < end; e++) {
        int s = g_colsrc[e];
        acc = fmaf(g_dis[s], __half2float(H[(size_t)s * 32 + lane]), acc);
    }
    acc *= di;
    if constexpr (EPI) acc = fmaxf(acc + B[lane], 0.f);
    if constexpr (OUTF) outf[(size_t)gw * 32 + lane] = acc;
    else               outh[(size_t)gw * 32 + lane] = __float2half(acc);
}

// ---------------- agg F=128: half gather -> fp32 accumulate -> half out ----------------
__device__ __forceinline__ float4 h4_to_f4(uint2 v) {
    __half2 a = *(__half2*)&v.x, b = *(__half2*)&v.y;
    float2 fa = __half22float2(a), fb = __half22float2(b);
    return make_float4(fa.x, fa.y, fb.x, fb.y);
}

__global__ __launch_bounds__(256) void agg128h_kernel(
    const __half* __restrict__ H, __half* __restrict__ out, int N)
{
    int gw = (blockIdx.x * 256 + threadIdx.x) >> 5;
    int lane = threadIdx.x & 31;
    if (gw >= N) return;
    const float di = g_dis[gw];
    const int beg = g_rowptr[gw], end = g_rowptr[gw + 1];

    float4 h0 = h4_to_f4(((const uint2*)(H + (size_t)gw * 128))[lane]);
    float4 acc = make_float4(di * h0.x, di * h0.y, di * h0.z, di * h0.w);
    int e = beg;
    for (; e + 4 <= end; e += 4) {
        int s0 = g_colsrc[e], s1 = g_colsrc[e + 1];
        int s2 = g_colsrc[e + 2], s3 = g_colsrc[e + 3];
        float w0 = g_dis[s0], w1 = g_dis[s1], w2 = g_dis[s2], w3 = g_dis[s3];
        float4 v0 = h4_to_f4(((const uint2*)(H + (size_t)s0 * 128))[lane]);
        float4 v1 = h4_to_f4(((const uint2*)(H + (size_t)s1 * 128))[lane]);
        float4 v2 = h4_to_f4(((const uint2*)(H + (size_t)s2 * 128))[lane]);
        float4 v3 = h4_to_f4(((const uint2*)(H + (size_t)s3 * 128))[lane]);
        acc.x = fmaf(w0, v0.x, acc.x); acc.y = fmaf(w0, v0.y, acc.y);
        acc.z = fmaf(w0, v0.z, acc.z); acc.w = fmaf(w0, v0.w, acc.w);
        acc.x = fmaf(w1, v1.x, acc.x); acc.y = fmaf(w1, v1.y, acc.y);
        acc.z = fmaf(w1, v1.z, acc.z); acc.w = fmaf(w1, v1.w, acc.w);
        acc.x = fmaf(w2, v2.x, acc.x); acc.y = fmaf(w2, v2.y, acc.y);
        acc.z = fmaf(w2, v2.z, acc.z); acc.w = fmaf(w2, v2.w, acc.w);
        acc.x = fmaf(w3, v3.x, acc.x); acc.y = fmaf(w3, v3.y, acc.y);
        acc.z = fmaf(w3, v3.z, acc.z); acc.w = fmaf(w3, v3.w, acc.w);
    }
    for (; e < end; e++) {
        int s = g_colsrc[e];
        float w = g_dis[s];
        float4 v = h4_to_f4(((const uint2*)(H + (size_t)s * 128))[lane]);
        acc.x = fmaf(w, v.x, acc.x); acc.y = fmaf(w, v.y, acc.y);
        acc.z = fmaf(w, v.z, acc.z); acc.w = fmaf(w, v.w, acc.w);
    }
    __half2 o01 = __floats2half2_rn(di * acc.x, di * acc.y);
    __half2 o23 = __floats2half2_rn(di * acc.z, di * acc.w);
    uint2 pk = make_uint2(*(unsigned*)&o01, *(unsigned*)&o23);
    ((uint2*)(out + (size_t)gw * 128))[lane] = pk;
}

extern "C" void kernel_launch(void* const* d_in, const int* in_sizes, int n_in,
                              void* d_out, int out_size) {
    const float* x  = (const float*)d_in[0];
    const void*  ed = d_in[1];
    const float* W1 = (const float*)d_in[2];
    const float* b1 = (const float*)d_in[3];
    const float* W2 = (const float*)d_in[4];
    const float* b2 = (const float*)d_in[5];
    const float* W3 = (const float*)d_in[6];
    const float* b3 = (const float*)d_in[7];
    float* out = (float*)d_out;

    const int N = in_sizes[0] / 32;
    const int E = in_sizes[1] / 2;
    const int nb = (N + 1023) / 1024;

    __half *xh, *s32h, *h16, *hB, *hA, *s3h;
    cudaGetSymbolAddress((void**)&xh,   g_xh);
    cudaGetSymbolAddress((void**)&s32h, g_s32h);
    cudaGetSymbolAddress((void**)&h16,  g_h16);
    cudaGetSymbolAddress((void**)&hB,   g_hB);
    cudaGetSymbolAddress((void**)&hA,   g_hA);
    cudaGetSymbolAddress((void**)&s3h,  g_s3h);

    const int eblk = (E + 255) / 256;
    const int ablk = (N * 32 + 255) / 256;     // warp per node
    const int pblk = (N * 32 + 255) / 256;

    // dynamic smem sizes (halves): As MBLK*(K+8) + Bs K*(NOUT+8)
    const int sm1 = (128 * 40 + 32 * 136) * 2;   // 18944
    const int sm2 = (128 * 136 + 128 * 136) * 2; // 69632
    const int sm3 = (256 * 136 + 128 * 40) * 2;  // 79872
    cudaFuncSetAttribute(wgemm<32, 128, true>,  cudaFuncAttributeMaxDynamicSharedMemorySize, sm1);
    cudaFuncSetAttribute(wgemm<128, 128, true>, cudaFuncAttributeMaxDynamicSharedMemorySize, sm2);
    cudaFuncSetAttribute(wgemm<128, 32, false>, cudaFuncAttributeMaxDynamicSharedMemorySize, sm3);

    // CSR + norm build
    k_prep<<<pblk, 256>>>(x, (const int*)ed, N, E);
    k_count<<<eblk, 256>>>(ed, E, N);
    scan_reduce<<<nb, 1024>>>(N);
    scan_top<<<1, 32>>>(nb, N);
    scan_write<<<nb, 1024>>>(N);
    fill_csr<<<eblk, 256>>>(ed, E, N);

    // L1: relu(Agg(x) @ W1 + b1)
    agg32_kernel<false, false><<<ablk, 256>>>(xh, nullptr, s32h, nullptr, N);
    wgemm<32, 128, true><<<(N + 127) / 128, 256, sm1>>>(s32h, W1, b1, h16);

    // L2: relu(Agg(h1) @ W2 + b2)
    agg128h_kernel<<<ablk, 256>>>(h16, hB, N);
    wgemm<128, 128, true><<<(N + 127) / 128, 256, sm2>>>(hB, W2, b2, hA);

    // L3: relu(Agg(h2 @ W3) + b3)  (transform first: aggregate at 32 features)
    wgemm<128, 32, false><<<(N + 255) / 256, 256, sm3>>>(hA, W3, nullptr, s3h);
    agg32_kernel<true, true><<<ablk, 256>>>(s3h, b3, nullptr, out, N);
}